// round 5
// baseline (speedup 1.0000x reference)
#include <cuda_runtime.h>
#include <cuda_bf16.h>
#include <mma.h>
#include <cuda_pipeline.h>
#include <cstdint>

using namespace nvcuda;

// Problem dims
#define M_TOT 8192          // 4*2048
#define N_TOT 14336
#define K_TOT 4096
#define MP    16384         // M doubled: interleaved hi/lo int8 rows
#define NPACK (N_TOT * (K_TOT / 2))

// GEMM tiling (int8 wmma 16x16x16)
#define BM 128              // A' rows per CTA (= 64 output rows)
#define BN 128
#define BK 64               // int8 k per stage (64 bytes/row)
#define LDT 80              // smem row stride bytes (64 + 16 pad, 8B-aligned chunks)
#define NK (K_TOT / BK)     // 64 k-iterations

// Scratch (static device globals: allocation-free per harness rules)
__device__ __align__(256) signed char g_Ai[(size_t)MP * K_TOT];     // 67 MB interleaved hi/lo
__device__ __align__(256) signed char g_Qi[(size_t)N_TOT * K_TOT];  // 59 MB unpacked weights
__device__ float g_srow[M_TOT];                                     // per-row x scale
__device__ int g_swap_sb;   // 1 => sb0 is actually bias
__device__ int g_qw_i32;    // 1 => qweight stored as int32 (harness promoted int8)

// ---------------------------------------------------------------------------
// Probes: scale strictly positive (abs-max/7) vs bias (has negatives);
// qweight dtype: int32-promoted iff first 4096 words all in [-128,127].
// ---------------------------------------------------------------------------
__global__ void probe_kernel(const float* __restrict__ sb0,
                             const void* __restrict__ qw_raw) {
    __shared__ int s_neg, s_small;
    if (threadIdx.x == 0) { s_neg = 0; s_small = 1; }
    __syncthreads();
    int local_neg = 0;
    for (int i = threadIdx.x; i < N_TOT; i += blockDim.x)
        if (sb0[i] < 0.0f) local_neg = 1;
    if (local_neg) atomicOr(&s_neg, 1);
    const int* qw32 = (const int*)qw_raw;
    int local_big = 0;
    for (int i = threadIdx.x; i < 4096; i += blockDim.x) {
        int v = qw32[i];
        if (v < -128 || v > 127) local_big = 1;
    }
    if (local_big) atomicAnd(&s_small, 0);
    __syncthreads();
    if (threadIdx.x == 0) { g_swap_sb = s_neg; g_qw_i32 = s_small; }
}

// ---------------------------------------------------------------------------
// Prep A: one block per output row m. Row abs-max -> scale, quantize x to
// int16 range [-32639,32639], split int16 = 256*hi + lo (both int8), write
// interleaved layout: A'[16g + r] = hi, A'[16g + 8 + r] = lo, m = 8g + r.
// ---------------------------------------------------------------------------
__global__ __launch_bounds__(256) void prep_a_kernel(const float* __restrict__ x) {
    const int m = blockIdx.x;
    const float* xr = x + (size_t)m * K_TOT;
    __shared__ float s_max[8];

    float mx = 0.0f;
    for (int k = threadIdx.x; k < K_TOT; k += 256)
        mx = fmaxf(mx, fabsf(xr[k]));
    #pragma unroll
    for (int o = 16; o > 0; o >>= 1)
        mx = fmaxf(mx, __shfl_xor_sync(0xFFFFFFFFu, mx, o));
    if ((threadIdx.x & 31) == 0) s_max[threadIdx.x >> 5] = mx;
    __syncthreads();
    if (threadIdx.x < 8) {
        float v = s_max[threadIdx.x];
        #pragma unroll
        for (int o = 4; o > 0; o >>= 1)
            v = fmaxf(v, __shfl_xor_sync(0xFFu, v, o));
        if (threadIdx.x == 0) s_max[0] = fmaxf(v, 1e-30f);
    }
    __syncthreads();
    const float maxv = s_max[0];
    const float inv = 32639.0f / maxv;
    if (threadIdx.x == 0) g_srow[m] = maxv / 32639.0f;

    const int g = m >> 3, r = m & 7;
    signed char* hi_row = g_Ai + ((size_t)((g << 4) + r)) * K_TOT;
    signed char* lo_row = g_Ai + ((size_t)((g << 4) + 8 + r)) * K_TOT;
    for (int k = threadIdx.x; k < K_TOT; k += 256) {
        int xi = __float2int_rn(xr[k] * inv);
        xi = max(-32639, min(32639, xi));
        int lo = ((xi & 255) ^ 128) - 128;         // signed low byte
        int hi = (xi - lo) >> 8;                   // fits [-127,127]
        hi_row[k] = (signed char)hi;
        lo_row[k] = (signed char)lo;
    }
}

// ---------------------------------------------------------------------------
// Prep B: unpack 4-bit pairs -> int8 in [-8,7].
// Packed byte j of row n: high nibble = q[n][2j], low = q[n][2j+1].
// ---------------------------------------------------------------------------
__global__ void unpack_w_kernel(const void* __restrict__ qw_raw) {
    int idx = blockIdx.x * blockDim.x + threadIdx.x;
    if (idx >= NPACK) return;
    int v;
    if (g_qw_i32) v = ((const int*)qw_raw)[idx];
    else          v = (int)((const signed char*)qw_raw)[idx];
    int n = idx / (K_TOT / 2);
    int j = idx - n * (K_TOT / 2);
    g_Qi[(size_t)n * K_TOT + 2 * j]     = (signed char)(v >> 4);
    g_Qi[(size_t)n * K_TOT + 2 * j + 1] = (signed char)(((v & 15) ^ 8) - 8);
}

// ---------------------------------------------------------------------------
// INT8 GEMM: C'[R,n] = sum_k A'[R,k]*Q[n,k]  (s8*s8 -> s32, exact)
// out[m,n] = s_m * scale_n * (256*C'[hi(m),n] + C'[lo(m),n]) + bias_n
// 128x128 A'-tile (=64 output rows), BK=64, 8 warps 2x4, warp tile 64x32.
// cp.async (8B) double-buffered; epilogue pairs rows r / r+8 in staged tile.
// ---------------------------------------------------------------------------
__global__ __launch_bounds__(256, 2) void gemm_i8_kernel(const float* __restrict__ sb0,
                                                         const float* __restrict__ sb1,
                                                         float* __restrict__ out) {
    __shared__ __align__(16) signed char As[2][BM * LDT];   // 2 x 10240
    __shared__ __align__(16) signed char Bs[2][BN * LDT];
    __shared__ float s_scale[BN], s_bias[BN], s_srow[BM / 2];

    const int tid = threadIdx.x;
    const int m0p = blockIdx.x * BM;        // A' row base (m fastest for L2 reuse of B)
    const int n0  = blockIdx.y * BN;

    {   // stage scale/bias/srow
        const float* scale = g_swap_sb ? sb1 : sb0;
        const float* bias  = g_swap_sb ? sb0 : sb1;
        if (tid < BN) { s_scale[tid] = scale[n0 + tid]; s_bias[tid] = bias[n0 + tid]; }
        else if (tid < BN + BM / 2) s_srow[tid - BN] = g_srow[m0p / 2 + tid - BN];
    }

    // per-stage: A 128 rows x 64B + B same; 8B chunks: 1024 + 1024, 8/thread
    auto issue = [&](int t, int buf) {
        const int k0 = t * BK;
        #pragma unroll
        for (int c = 0; c < 4; ++c) {
            int g = c * 256 + tid;
            int row = g >> 3, col = (g & 7) * 8;
            __pipeline_memcpy_async(&As[buf][row * LDT + col],
                                    g_Ai + (size_t)(m0p + row) * K_TOT + k0 + col, 8);
        }
        #pragma unroll
        for (int c = 0; c < 4; ++c) {
            int g = c * 256 + tid;
            int row = g >> 3, col = (g & 7) * 8;
            __pipeline_memcpy_async(&Bs[buf][row * LDT + col],
                                    g_Qi + (size_t)(n0 + row) * K_TOT + k0 + col, 8);
        }
    };

    const int warpId = tid >> 5;
    const int lane   = tid & 31;
    const int wm = (warpId & 1) * 64;    // A' rows
    const int wn = (warpId >> 1) * 32;

    wmma::fragment<wmma::matrix_a, 16, 16, 16, signed char, wmma::row_major> fa[4];
    wmma::fragment<wmma::matrix_b, 16, 16, 16, signed char, wmma::col_major> fb[2];
    wmma::fragment<wmma::accumulator, 16, 16, 16, int> acc[4][2];
    #pragma unroll
    for (int i = 0; i < 4; ++i)
        #pragma unroll
        for (int j = 0; j < 2; ++j)
            wmma::fill_fragment(acc[i][j], 0);

    issue(0, 0);
    __pipeline_commit();

    int buf = 0;
    for (int t = 0; t < NK; ++t) {
        if (t + 1 < NK) {
            issue(t + 1, buf ^ 1);
            __pipeline_commit();
        }
        __pipeline_wait_prior((t + 1 < NK) ? 1 : 0);
        __syncthreads();

        #pragma unroll
        for (int kk = 0; kk < BK; kk += 16) {
            #pragma unroll
            for (int i = 0; i < 4; ++i)
                wmma::load_matrix_sync(fa[i], &As[buf][(wm + i * 16) * LDT + kk], LDT);
            #pragma unroll
            for (int j = 0; j < 2; ++j)
                wmma::load_matrix_sync(fb[j], &Bs[buf][(wn + j * 16) * LDT + kk], LDT);
            #pragma unroll
            for (int i = 0; i < 4; ++i)
                #pragma unroll
                for (int j = 0; j < 2; ++j)
                    wmma::mma_sync(acc[i][j], fa[i], fb[j], acc[i][j]);
        }
        __syncthreads();
        buf ^= 1;
    }

    // Epilogue: stage each 16x16 int tile; rows r(hi) and r+8(lo) pair to one
    // output row: val = 256*hi + lo (exact, < 2^31).
    __syncthreads();
    int* cbuf = reinterpret_cast<int*>(&As[0][0]) + warpId * 256;  // 1KB/warp

    #pragma unroll
    for (int i = 0; i < 4; ++i) {
        #pragma unroll
        for (int j = 0; j < 2; ++j) {
            wmma::store_matrix_sync(cbuf, acc[i][j], 16, wmma::mem_row_major);
            __syncwarp();
            const int wm0 = wm + i * 16;              // CTA-local A' row base (mult of 16)
            const int lmbase = wm0 >> 1;              // local output row base (8 rows)
            const int lnbase = wn + j * 16;
            #pragma unroll
            for (int e = lane; e < 128; e += 32) {
                int r = e >> 4, c = e & 15;
                int val = 256 * cbuf[r * 16 + c] + cbuf[(r + 8) * 16 + c];
                int lm = lmbase + r;
                int ln = lnbase + c;
                size_t om = (size_t)(m0p / 2 + lm) * N_TOT + (n0 + ln);
                out[om] = s_srow[lm] * s_scale[ln] * (float)val + s_bias[ln];
            }
            __syncwarp();
        }
    }
}

// ---------------------------------------------------------------------------
extern "C" void kernel_launch(void* const* d_in, const int* in_sizes, int n_in,
                              void* d_out, int out_size) {
    (void)out_size;
    // Bind by element count: x 33554432 | qweight 29360128 | scale/bias 14336
    int ix = 0, iq = 1, isb0 = 2, isb1 = 3, nsb = 0;
    int sb_idx[2] = {2, 3};
    for (int i = 0; i < n_in && i < 8; ++i) {
        if (in_sizes[i] == M_TOT * K_TOT) ix = i;
        else if (in_sizes[i] == NPACK) iq = i;
        else if (in_sizes[i] == N_TOT && nsb < 2) sb_idx[nsb++] = i;
    }
    if (nsb == 2) { isb0 = sb_idx[0]; isb1 = sb_idx[1]; }

    const float* x   = (const float*)d_in[ix];
    const void*  qw  = d_in[iq];
    const float* sb0 = (const float*)d_in[isb0];
    const float* sb1 = (const float*)d_in[isb1];
    float*       out = (float*)d_out;

    probe_kernel<<<1, 1024>>>(sb0, qw);
    prep_a_kernel<<<M_TOT, 256>>>(x);
    unpack_w_kernel<<<(NPACK + 255) / 256, 256>>>(qw);

    dim3 grid(MP / BM, N_TOT / BN);   // (128, 112), m fastest
    gemm_i8_kernel<<<grid, 256>>>(sb0, sb1, out);
}

// round 6
// speedup vs baseline: 8.7100x; 8.7100x over previous
#include <cuda_runtime.h>
#include <cuda_fp16.h>
#include <mma.h>
#include <cuda_pipeline.h>
#include <cstdint>

using namespace nvcuda;

// Problem dims
#define M_TOT 8192          // 4*2048
#define N_TOT 14336
#define K_TOT 4096
#define NPACK (N_TOT * (K_TOT / 2))

// GEMM tiling (fp16 wmma 16x16x16, single K pass)
#define BM 128
#define BN 128
#define BK 64               // 64 fp16 per stage row (128B)
#define LDT 72              // smem row stride (halves): 64 + 8 pad (16B-aligned rows)
#define NT (K_TOT / BK)     // 64 k-iterations
#define STAGES 3
#define STAGE_HALVES ((BM + BN) * LDT)              // 18432 halves = 36864 B
#define SMEM_BYTES (STAGES * STAGE_HALVES * 2)      // 110592 B dynamic

// Scratch (static device globals: allocation-free per harness rules)
__device__ __align__(256) __half g_Ah[(size_t)M_TOT * K_TOT];   // 67 MB: x in fp16
__device__ __align__(256) __half g_Qh[(size_t)N_TOT * K_TOT];   // 117 MB: weights fp16
__device__ int g_swap_sb;   // 1 => sb0 is actually bias
__device__ int g_qw_i32;    // 1 => qweight stored as int32 (harness promoted int8)

// ---------------------------------------------------------------------------
// Probes: scale strictly positive (abs-max/7) vs bias (has negatives);
// qweight dtype: int32-promoted iff first 4096 words all in [-128,127].
// ---------------------------------------------------------------------------
__global__ void probe_kernel(const float* __restrict__ sb0,
                             const void* __restrict__ qw_raw) {
    __shared__ int s_neg, s_small;
    if (threadIdx.x == 0) { s_neg = 0; s_small = 1; }
    __syncthreads();
    int local_neg = 0;
    for (int i = threadIdx.x; i < N_TOT; i += blockDim.x)
        if (sb0[i] < 0.0f) local_neg = 1;
    if (local_neg) atomicOr(&s_neg, 1);
    const int* qw32 = (const int*)qw_raw;
    int local_big = 0;
    for (int i = threadIdx.x; i < 4096; i += blockDim.x) {
        int v = qw32[i];
        if (v < -128 || v > 127) local_big = 1;
    }
    if (local_big) atomicAnd(&s_small, 0);
    __syncthreads();
    if (threadIdx.x == 0) { g_swap_sb = s_neg; g_qw_i32 = s_small; }
}

// ---------------------------------------------------------------------------
// Prep 1: x fp32 -> fp16 (round-to-nearest). Per-term rel err ~2.8e-4 rms,
// output rel err ~3e-4 (incoherent accumulation) — under the 1e-3 threshold.
// ---------------------------------------------------------------------------
__global__ void conv_x_kernel(const float* __restrict__ x) {
    int idx = blockIdx.x * blockDim.x + threadIdx.x;
    if (idx >= M_TOT * K_TOT) return;
    g_Ah[idx] = __float2half_rn(x[idx]);
}

// ---------------------------------------------------------------------------
// Prep 2: unpack 4-bit pairs -> fp16 integers in [-8,7] (exact in fp16).
// Packed byte j of row n: high nibble = q[n][2j], low = q[n][2j+1].
// ---------------------------------------------------------------------------
__global__ void unpack_w_kernel(const void* __restrict__ qw_raw) {
    int idx = blockIdx.x * blockDim.x + threadIdx.x;
    if (idx >= NPACK) return;
    int v;
    if (g_qw_i32) v = ((const int*)qw_raw)[idx];
    else          v = (int)((const signed char*)qw_raw)[idx];
    int n = idx / (K_TOT / 2);
    int j = idx - n * (K_TOT / 2);
    int hi = v >> 4;
    int lo = ((v & 15) ^ 8) - 8;
    g_Qh[(size_t)n * K_TOT + 2 * j]     = __float2half_rn((float)hi);
    g_Qh[(size_t)n * K_TOT + 2 * j + 1] = __float2half_rn((float)lo);
}

// ---------------------------------------------------------------------------
// GEMM: out[m,n] = scale[n] * sum_k Ah[m,k]*Qh[n,k] + bias[n]
// 128x128 tile, BK=64, 3-stage cp.async, ONE __syncthreads per k-iter.
// 8 warps (2x4), warp tile 64x32, wmma 16x16x16 half->float.
// ---------------------------------------------------------------------------
__global__ __launch_bounds__(256) void gemm_f16_kernel(const float* __restrict__ sb0,
                                                       const float* __restrict__ sb1,
                                                       float* __restrict__ out) {
    extern __shared__ __align__(16) char dsm[];
    __half* smem_h = reinterpret_cast<__half*>(dsm);

    const int tid = threadIdx.x;
    const int n0 = blockIdx.x * BN;
    const int m0 = blockIdx.y * BM;

    auto Abuf = [&](int s) { return smem_h + s * STAGE_HALVES; };
    auto Bbuf = [&](int s) { return smem_h + s * STAGE_HALVES + BM * LDT; };

    // Per stage: A = 128 rows x 8 chunks(16B) = 1024 chunks, B same.
    // 256 threads x 4 chunks each per matrix.
    auto issue = [&](int t) {
        const int s = t % STAGES;
        const int k0 = t * BK;
        __half* Ab = Abuf(s);
        __half* Bb = Bbuf(s);
        #pragma unroll
        for (int c = 0; c < 4; ++c) {
            int g = c * 256 + tid;
            int row = g >> 3, col = (g & 7) * 8;     // halves
            __pipeline_memcpy_async(Ab + row * LDT + col,
                                    g_Ah + (size_t)(m0 + row) * K_TOT + k0 + col, 16);
        }
        #pragma unroll
        for (int c = 0; c < 4; ++c) {
            int g = c * 256 + tid;
            int row = g >> 3, col = (g & 7) * 8;
            __pipeline_memcpy_async(Bb + row * LDT + col,
                                    g_Qh + (size_t)(n0 + row) * K_TOT + k0 + col, 16);
        }
    };

    const int warpId = tid >> 5;
    const int lane   = tid & 31;
    const int wm = (warpId & 1) * 64;   // 2 warps along M
    const int wn = (warpId >> 1) * 32;  // 4 warps along N

    wmma::fragment<wmma::matrix_a, 16, 16, 16, __half, wmma::row_major> fa[4];
    wmma::fragment<wmma::matrix_b, 16, 16, 16, __half, wmma::col_major> fb[2];
    wmma::fragment<wmma::accumulator, 16, 16, 16, float> acc[4][2];
    #pragma unroll
    for (int i = 0; i < 4; ++i)
        #pragma unroll
        for (int j = 0; j < 2; ++j)
            wmma::fill_fragment(acc[i][j], 0.0f);

    issue(0); __pipeline_commit();
    issue(1); __pipeline_commit();

    for (int t = 0; t < NT; ++t) {
        __pipeline_wait_prior((t + 1 < NT) ? 1 : 0);   // group t complete
        __syncthreads();                               // all warps done with t-1; t visible
        if (t + 2 < NT) {                              // refill buffer (t-1)%3 — now safe
            issue(t + 2);
            __pipeline_commit();
        }
        const __half* As = Abuf(t % STAGES);
        const __half* Bs = Bbuf(t % STAGES);
        #pragma unroll
        for (int kk = 0; kk < BK; kk += 16) {
            #pragma unroll
            for (int i = 0; i < 4; ++i)
                wmma::load_matrix_sync(fa[i], As + (wm + i * 16) * LDT + kk, LDT);
            #pragma unroll
            for (int j = 0; j < 2; ++j)
                wmma::load_matrix_sync(fb[j], Bs + (wn + j * 16) * LDT + kk, LDT);
            #pragma unroll
            for (int i = 0; i < 4; ++i)
                #pragma unroll
                for (int j = 0; j < 2; ++j)
                    wmma::mma_sync(acc[i][j], fa[i], fb[j], acc[i][j]);
        }
    }

    // Epilogue: stage 16x16 tiles through per-warp smem, fuse scale/bias.
    __syncthreads();
    const float* scale = g_swap_sb ? sb1 : sb0;
    const float* bias  = g_swap_sb ? sb0 : sb1;
    float* cbuf = reinterpret_cast<float*>(dsm) + warpId * 256;   // 1KB/warp

    #pragma unroll
    for (int i = 0; i < 4; ++i) {
        #pragma unroll
        for (int j = 0; j < 2; ++j) {
            wmma::store_matrix_sync(cbuf, acc[i][j], 16, wmma::mem_row_major);
            __syncwarp();
            const int gm_base = m0 + wm + i * 16;
            const int gn_base = n0 + wn + j * 16;
            #pragma unroll
            for (int e = lane; e < 256; e += 32) {
                int r = e >> 4, c = e & 15;
                int gn = gn_base + c;
                out[(size_t)(gm_base + r) * N_TOT + gn] = cbuf[e] * scale[gn] + bias[gn];
            }
            __syncwarp();
        }
    }
}

// ---------------------------------------------------------------------------
extern "C" void kernel_launch(void* const* d_in, const int* in_sizes, int n_in,
                              void* d_out, int out_size) {
    (void)out_size;
    // Bind by element count: x 33554432 | qweight 29360128 | scale/bias 14336
    int ix = 0, iq = 1, isb0 = 2, isb1 = 3, nsb = 0;
    int sb_idx[2] = {2, 3};
    for (int i = 0; i < n_in && i < 8; ++i) {
        if (in_sizes[i] == M_TOT * K_TOT) ix = i;
        else if (in_sizes[i] == NPACK) iq = i;
        else if (in_sizes[i] == N_TOT && nsb < 2) sb_idx[nsb++] = i;
    }
    if (nsb == 2) { isb0 = sb_idx[0]; isb1 = sb_idx[1]; }

    const float* x   = (const float*)d_in[ix];
    const void*  qw  = d_in[iq];
    const float* sb0 = (const float*)d_in[isb0];
    const float* sb1 = (const float*)d_in[isb1];
    float*       out = (float*)d_out;

    probe_kernel<<<1, 1024>>>(sb0, qw);

    const int totalA = M_TOT * K_TOT;
    conv_x_kernel<<<(totalA + 255) / 256, 256>>>(x);
    unpack_w_kernel<<<(NPACK + 255) / 256, 256>>>(qw);

    cudaFuncSetAttribute(gemm_f16_kernel,
                         cudaFuncAttributeMaxDynamicSharedMemorySize, SMEM_BYTES);
    dim3 grid(N_TOT / BN, M_TOT / BM);   // (112, 64)
    gemm_f16_kernel<<<grid, 256, SMEM_BYTES>>>(sb0, sb1, out);
}